// round 6
// baseline (speedup 1.0000x reference)
#include <cuda_runtime.h>
#include <math.h>

#define NN   50000
#define NE   800000
#define DIM  128
#define HID  128
#define ODIM 64
#define NL   3
#define NPB  8   // nodes per block in dense kernels

typedef unsigned long long u64;

// Scratch (no allocation allowed)
__device__ float g_h[(size_t)NN * HID];
__device__ float g_agg[(size_t)NN * HID];
__device__ float g_cnt[NN];
// Transposed weights: WT[c][k] = W[k][c]
__device__ float g_inWT[DIM * HID];
__device__ float g_WlT[NL * HID * HID];
__device__ float g_WrT[NL * HID * HID];
__device__ float g_oWT[ODIM * HID];

__device__ __forceinline__ float gelu_f(float x) {
    return 0.5f * x * (1.0f + erff(x * 0.70710678118654752440f));
}

// packed fp32x2 fma: d = a*b + d (lanewise)
__device__ __forceinline__ void ffma2(u64& d, u64 a, u64 b) {
    asm("fma.rn.f32x2 %0, %1, %2, %0;" : "+l"(d) : "l"(a), "l"(b));
}
__device__ __forceinline__ float unpack_sum(u64 v) {
    float lo, hi;
    asm("mov.b64 {%0, %1}, %2;" : "=f"(lo), "=f"(hi) : "l"(v));
    return lo + hi;
}

// ---------------------------------------------------------------------------
// Tiled transpose: out[c][r] = in[r][c], R rows, C cols  (proven in R3)
// ---------------------------------------------------------------------------
__global__ __launch_bounds__(256) void tp_kernel(
    const float* __restrict__ in, float* __restrict__ out, int R, int C)
{
    __shared__ float t[32][33];
    int bx = blockIdx.x * 32, by = blockIdx.y * 32;
    int x = threadIdx.x, y = threadIdx.y;  // block (32, 8)
#pragma unroll
    for (int i = y; i < 32; i += 8) {
        int rr = by + i, cc = bx + x;
        if (rr < R && cc < C) t[i][x] = in[rr * C + cc];
    }
    __syncthreads();
#pragma unroll
    for (int i = y; i < 32; i += 8) {
        int rr = by + x, cc = bx + i;
        if (rr < R && cc < C) out[cc * R + rr] = t[x][i];
    }
}

// ---------------------------------------------------------------------------
// In-degree count: one thread per edge
// ---------------------------------------------------------------------------
__global__ __launch_bounds__(256) void count_kernel(const int* __restrict__ dst) {
    int e = blockIdx.x * blockDim.x + threadIdx.x;
    if (e < NE) atomicAdd(&g_cnt[dst[e]], 1.0f);
}

// ---------------------------------------------------------------------------
// Fused: layernorm(x) -> @ in_proj + b -> gelu -> g_h
// 8 rows/block of 128 threads; thread j = output column, FFMA2 along k.
// ---------------------------------------------------------------------------
__global__ __launch_bounds__(128) void input_kernel(
    const float* __restrict__ x,
    const float* __restrict__ lng, const float* __restrict__ lnb,
    const float* __restrict__ WT,  const float* __restrict__ pb)
{
    __shared__ __align__(16) float sm[NPB][DIM];
    int nb = blockIdx.x * NPB;
    int tid = threadIdx.x, w = tid >> 5, lane = tid & 31;

#pragma unroll
    for (int rr = 0; rr < 2; rr++) {
        int r = w + rr * 4;
        int node = nb + r;
        int c = lane * 4;
        float4 v = make_float4(0.f, 0.f, 0.f, 0.f);
        if (node < NN) v = *(const float4*)(x + (size_t)node * DIM + c);
        float s  = v.x + v.y + v.z + v.w;
        float sq = v.x*v.x + v.y*v.y + v.z*v.z + v.w*v.w;
#pragma unroll
        for (int o = 16; o > 0; o >>= 1) {
            s  += __shfl_xor_sync(0xffffffffu, s,  o);
            sq += __shfl_xor_sync(0xffffffffu, sq, o);
        }
        float m    = s * (1.0f / DIM);
        float rstd = rsqrtf(sq * (1.0f / DIM) - m * m + 1e-5f);
        float4 o4;
        o4.x = (v.x - m) * rstd * lng[c + 0] + lnb[c + 0];
        o4.y = (v.y - m) * rstd * lng[c + 1] + lnb[c + 1];
        o4.z = (v.z - m) * rstd * lng[c + 2] + lnb[c + 2];
        o4.w = (v.w - m) * rstd * lng[c + 3] + lnb[c + 3];
        *(float4*)&sm[r][c] = o4;
    }
    __syncthreads();

    int j = tid;
    u64 acc[NPB];
#pragma unroll
    for (int r = 0; r < NPB; r++) acc[r] = 0ull;

#pragma unroll 4
    for (int k = 0; k < DIM; k += 4) {
        ulonglong2 wv = *(const ulonglong2*)(WT + (size_t)j * DIM + k);
#pragma unroll
        for (int r = 0; r < NPB; r++) {
            ulonglong2 hv = *(const ulonglong2*)&sm[r][k];
            ffma2(acc[r], hv.x, wv.x);
            ffma2(acc[r], hv.y, wv.y);
        }
    }
    float b0 = pb[j];
#pragma unroll
    for (int r = 0; r < NPB; r++) {
        int node = nb + r;
        if (node < NN) g_h[(size_t)node * HID + j] = gelu_f(unpack_sum(acc[r]) + b0);
    }
}

// ---------------------------------------------------------------------------
// Scatter-add: warp per edge, vector red.global.add.v4.f32
// ---------------------------------------------------------------------------
__global__ __launch_bounds__(256) void scatter_kernel(
    const int* __restrict__ src, const int* __restrict__ dst)
{
    int idx = blockIdx.x * blockDim.x + threadIdx.x;
    int e = idx >> 5;
    if (e >= NE) return;
    int c = (idx & 31) * 4;
    int s = __ldg(src + e);
    int d = __ldg(dst + e);
    float4 v = *(const float4*)(g_h + (size_t)s * HID + c);
    float* p = g_agg + (size_t)d * HID + c;
    asm volatile("red.global.add.v4.f32 [%0], {%1, %2, %3, %4};"
                 :: "l"(p), "f"(v.x), "f"(v.y), "f"(v.z), "f"(v.w)
                 : "memory");
}

// ---------------------------------------------------------------------------
// Fused SAGE tail: mean@Wl + bl + h@Wr -> LN -> gelu -> +h -> g_h
// 8 rows/block, thread j = output column, FFMA2 along k.
// ---------------------------------------------------------------------------
__global__ __launch_bounds__(128) void combine_kernel(
    const float* __restrict__ WlT, const float* __restrict__ bl,
    const float* __restrict__ WrT,
    const float* __restrict__ ng,  const float* __restrict__ nbeta)
{
    __shared__ __align__(16) float sm_m[NPB][DIM];
    __shared__ __align__(16) float sm_r[NPB][DIM];
    int nb = blockIdx.x * NPB;
    int tid = threadIdx.x, w = tid >> 5, lane = tid & 31;

    // Phase 1: mean = agg/max(cnt,1), root = h -> smem (2 rows per warp)
#pragma unroll
    for (int rr = 0; rr < 2; rr++) {
        int r = w + rr * 4;
        int node = nb + r;
        int c = lane * 4;
        float4 a = make_float4(0.f, 0.f, 0.f, 0.f);
        float4 h = make_float4(0.f, 0.f, 0.f, 0.f);
        float inv = 0.f;
        if (node < NN) {
            inv = 1.0f / fmaxf(g_cnt[node], 1.0f);
            a = *(const float4*)(g_agg + (size_t)node * HID + c);
            h = *(const float4*)(g_h   + (size_t)node * HID + c);
        }
        a.x *= inv; a.y *= inv; a.z *= inv; a.w *= inv;
        *(float4*)&sm_m[r][c] = a;
        *(float4*)&sm_r[r][c] = h;
    }
    __syncthreads();

    // Phase 2: dual matvec, thread j = output column, 8 rows
    int j = tid;
    u64 acc[NPB];
#pragma unroll
    for (int r = 0; r < NPB; r++) acc[r] = 0ull;

#pragma unroll 4
    for (int k = 0; k < DIM; k += 4) {
        ulonglong2 wl = *(const ulonglong2*)(WlT + (size_t)j * DIM + k);
        ulonglong2 wr = *(const ulonglong2*)(WrT + (size_t)j * DIM + k);
#pragma unroll
        for (int r = 0; r < NPB; r++) {
            ulonglong2 mv = *(const ulonglong2*)&sm_m[r][k];
            ulonglong2 hv = *(const ulonglong2*)&sm_r[r][k];
            ffma2(acc[r], mv.x, wl.x);
            ffma2(acc[r], mv.y, wl.y);
            ffma2(acc[r], hv.x, wr.x);
            ffma2(acc[r], hv.y, wr.y);
        }
    }
    __syncthreads();   // all reads of sm_m done before overwrite

    float b0 = bl[j];
#pragma unroll
    for (int r = 0; r < NPB; r++) sm_m[r][j] = unpack_sum(acc[r]) + b0;
    __syncthreads();

    // Phase 3: LN + gelu + residual -> g_h (2 rows per warp)
#pragma unroll
    for (int rr = 0; rr < 2; rr++) {
        int r = w + rr * 4;
        int node = nb + r;
        int c = lane * 4;
        float4 v = *(const float4*)&sm_m[r][c];
        float s  = v.x + v.y + v.z + v.w;
        float sq = v.x*v.x + v.y*v.y + v.z*v.z + v.w*v.w;
#pragma unroll
        for (int o = 16; o > 0; o >>= 1) {
            s  += __shfl_xor_sync(0xffffffffu, s,  o);
            sq += __shfl_xor_sync(0xffffffffu, sq, o);
        }
        float m    = s * (1.0f / HID);
        float rstd = rsqrtf(sq * (1.0f / HID) - m * m + 1e-5f);
        float4 hres = *(const float4*)&sm_r[r][c];
        float4 o4;
        o4.x = gelu_f((v.x - m) * rstd * ng[c + 0] + nbeta[c + 0]) + hres.x;
        o4.y = gelu_f((v.y - m) * rstd * ng[c + 1] + nbeta[c + 1]) + hres.y;
        o4.z = gelu_f((v.z - m) * rstd * ng[c + 2] + nbeta[c + 2]) + hres.z;
        o4.w = gelu_f((v.w - m) * rstd * ng[c + 3] + nbeta[c + 3]) + hres.w;
        if (node < NN) *(float4*)(g_h + (size_t)node * HID + c) = o4;
    }
}

// ---------------------------------------------------------------------------
// Fused: layernorm(h) @ out_proj + b -> out
// 8 rows/block; 64 cols -> col=tid&63, half=tid>>6 picks 4 rows. FFMA2.
// ---------------------------------------------------------------------------
__global__ __launch_bounds__(128) void final_kernel(
    const float* __restrict__ lng, const float* __restrict__ lnb,
    const float* __restrict__ WT,  const float* __restrict__ pb,
    float* __restrict__ out)
{
    __shared__ __align__(16) float sm[NPB][DIM];
    int nb = blockIdx.x * NPB;
    int tid = threadIdx.x, w = tid >> 5, lane = tid & 31;

#pragma unroll
    for (int rr = 0; rr < 2; rr++) {
        int r = w + rr * 4;
        int node = nb + r;
        int c = lane * 4;
        float4 v = make_float4(0.f, 0.f, 0.f, 0.f);
        if (node < NN) v = *(const float4*)(g_h + (size_t)node * HID + c);
        float s  = v.x + v.y + v.z + v.w;
        float sq = v.x*v.x + v.y*v.y + v.z*v.z + v.w*v.w;
#pragma unroll
        for (int o = 16; o > 0; o >>= 1) {
            s  += __shfl_xor_sync(0xffffffffu, s,  o);
            sq += __shfl_xor_sync(0xffffffffu, sq, o);
        }
        float m    = s * (1.0f / HID);
        float rstd = rsqrtf(sq * (1.0f / HID) - m * m + 1e-5f);
        float4 o4;
        o4.x = (v.x - m) * rstd * lng[c + 0] + lnb[c + 0];
        o4.y = (v.y - m) * rstd * lng[c + 1] + lnb[c + 1];
        o4.z = (v.z - m) * rstd * lng[c + 2] + lnb[c + 2];
        o4.w = (v.w - m) * rstd * lng[c + 3] + lnb[c + 3];
        *(float4*)&sm[r][c] = o4;
    }
    __syncthreads();

    int col  = tid & 63;
    int half = tid >> 6;  // 0: rows 0-3, 1: rows 4-7
    u64 acc[4];
#pragma unroll
    for (int r = 0; r < 4; r++) acc[r] = 0ull;

#pragma unroll 4
    for (int k = 0; k < HID; k += 4) {
        ulonglong2 wv = *(const ulonglong2*)(WT + (size_t)col * HID + k);
#pragma unroll
        for (int r = 0; r < 4; r++) {
            ulonglong2 hv = *(const ulonglong2*)&sm[half * 4 + r][k];
            ffma2(acc[r], hv.x, wv.x);
            ffma2(acc[r], hv.y, wv.y);
        }
    }
    float b0 = pb[col];
#pragma unroll
    for (int r = 0; r < 4; r++) {
        int node = nb + half * 4 + r;
        if (node < NN) out[(size_t)node * ODIM + col] = unpack_sum(acc[r]) + b0;
    }
}

// ---------------------------------------------------------------------------
extern "C" void kernel_launch(void* const* d_in, const int* in_sizes, int n_in,
                              void* d_out, int out_size)
{
    const float* x     = (const float*)d_in[0];
    const int*   ei    = (const int*)  d_in[1];
    const float* in_g  = (const float*)d_in[2];
    const float* in_b  = (const float*)d_in[3];
    const float* inW   = (const float*)d_in[4];
    const float* inPb  = (const float*)d_in[5];
    const float* Wl    = (const float*)d_in[6];
    const float* bl    = (const float*)d_in[7];
    const float* Wr    = (const float*)d_in[8];
    const float* ng    = (const float*)d_in[9];
    const float* nbta  = (const float*)d_in[10];
    const float* og    = (const float*)d_in[11];
    const float* ob    = (const float*)d_in[12];
    const float* oW    = (const float*)d_in[13];
    const float* oPb   = (const float*)d_in[14];
    float* out = (float*)d_out;

    const int* src = ei;
    const int* dst = ei + NE;

    void* cntp = nullptr;
    void* aggp = nullptr;
    void* inWTp = nullptr;
    void* WlTp = nullptr;
    void* WrTp = nullptr;
    void* oWTp = nullptr;
    cudaGetSymbolAddress(&cntp,  g_cnt);
    cudaGetSymbolAddress(&aggp,  g_agg);
    cudaGetSymbolAddress(&inWTp, g_inWT);
    cudaGetSymbolAddress(&WlTp,  g_WlT);
    cudaGetSymbolAddress(&WrTp,  g_WrT);
    cudaGetSymbolAddress(&oWTp,  g_oWT);
    float* inWT = (float*)inWTp;
    float* WlT  = (float*)WlTp;
    float* WrT  = (float*)WrTp;
    float* oWT  = (float*)oWTp;

    const int nblk = (NN + NPB - 1) / NPB;    // 6250
    const int sblk = (NE * 32 + 255) / 256;   // 100000

    // Weight transposes (proven R3-style kernel, 8 small launches)
    {
        dim3 b(32, 8);
        dim3 g128(4, 4);  // 128x128
        tp_kernel<<<g128, b>>>(inW, inWT, DIM, HID);
        for (int l = 0; l < NL; l++) {
            tp_kernel<<<g128, b>>>(Wl + (size_t)l * HID * HID, WlT + (size_t)l * HID * HID, HID, HID);
            tp_kernel<<<g128, b>>>(Wr + (size_t)l * HID * HID, WrT + (size_t)l * HID * HID, HID, HID);
        }
        dim3 g64(2, 4);   // 128x64
        tp_kernel<<<g64, b>>>(oW, oWT, HID, ODIM);
    }

    cudaMemsetAsync(cntp, 0, NN * sizeof(float));
    count_kernel<<<(NE + 255) / 256, 256>>>(dst);
    input_kernel<<<nblk, 128>>>(x, in_g, in_b, inWT, inPb);

    for (int l = 0; l < NL; l++) {
        cudaMemsetAsync(aggp, 0, (size_t)NN * HID * sizeof(float));
        scatter_kernel<<<sblk, 256>>>(src, dst);
        combine_kernel<<<nblk, 128>>>(WlT + (size_t)l * HID * HID,
                                      bl + l * HID,
                                      WrT + (size_t)l * HID * HID,
                                      ng + l * HID,
                                      nbta + l * HID);
    }

    final_kernel<<<nblk, 128>>>(og, ob, oWT, oPb, out);
}

// round 8
// speedup vs baseline: 1.8743x; 1.8743x over previous
#include <cuda_runtime.h>
#include <math.h>

#define NN   50000
#define NE   800000
#define DIM  128
#define HID  128
#define ODIM 64
#define NL   3
#define NPB  8   // nodes per block in dense kernels

// Scratch (no allocation allowed)
__device__ float g_h[(size_t)NN * HID];
__device__ float g_agg[(size_t)NN * HID];
__device__ float g_cnt[NN];

__device__ __forceinline__ float gelu_f(float x) {
    return 0.5f * x * (1.0f + erff(x * 0.70710678118654752440f));
}

// ---------------------------------------------------------------------------
// In-degree count: one thread per edge
// ---------------------------------------------------------------------------
__global__ __launch_bounds__(256) void count_kernel(const int* __restrict__ dst) {
    int e = blockIdx.x * blockDim.x + threadIdx.x;
    if (e < NE) atomicAdd(&g_cnt[dst[e]], 1.0f);
}

// ---------------------------------------------------------------------------
// Fused: layernorm(x) -> @ in_proj + b -> gelu -> g_h
// 8 nodes / block of 128 threads. (identical to R1-proven version)
// ---------------------------------------------------------------------------
__global__ __launch_bounds__(128) void input_kernel(
    const float* __restrict__ x,
    const float* __restrict__ lng, const float* __restrict__ lnb,
    const float* __restrict__ W,   const float* __restrict__ pb)
{
    __shared__ __align__(16) float sm[NPB][DIM];
    int nb = blockIdx.x * NPB;
    int tid = threadIdx.x, w = tid >> 5, lane = tid & 31;

#pragma unroll
    for (int rr = 0; rr < 2; rr++) {
        int r = w + rr * 4;
        int node = nb + r;
        int c = lane * 4;
        float4 v = make_float4(0.f, 0.f, 0.f, 0.f);
        if (node < NN) v = *(const float4*)(x + (size_t)node * DIM + c);
        float s  = v.x + v.y + v.z + v.w;
        float sq = v.x*v.x + v.y*v.y + v.z*v.z + v.w*v.w;
#pragma unroll
        for (int o = 16; o > 0; o >>= 1) {
            s  += __shfl_xor_sync(0xffffffffu, s,  o);
            sq += __shfl_xor_sync(0xffffffffu, sq, o);
        }
        float m    = s * (1.0f / DIM);
        float rstd = rsqrtf(sq * (1.0f / DIM) - m * m + 1e-5f);
        float4 o4;
        o4.x = (v.x - m) * rstd * lng[c + 0] + lnb[c + 0];
        o4.y = (v.y - m) * rstd * lng[c + 1] + lnb[c + 1];
        o4.z = (v.z - m) * rstd * lng[c + 2] + lnb[c + 2];
        o4.w = (v.w - m) * rstd * lng[c + 3] + lnb[c + 3];
        *(float4*)&sm[r][c] = o4;
    }
    __syncthreads();

    int j = tid;
    float bias = pb[j];
    float acc[NPB];
#pragma unroll
    for (int r = 0; r < NPB; r++) acc[r] = bias;

#pragma unroll 4
    for (int k = 0; k < DIM; k += 4) {
        float w0 = W[(k + 0) * HID + j];
        float w1 = W[(k + 1) * HID + j];
        float w2 = W[(k + 2) * HID + j];
        float w3 = W[(k + 3) * HID + j];
#pragma unroll
        for (int r = 0; r < NPB; r++) {
            float4 hv = *(const float4*)&sm[r][k];
            acc[r] += hv.x * w0 + hv.y * w1 + hv.z * w2 + hv.w * w3;
        }
    }
#pragma unroll
    for (int r = 0; r < NPB; r++) {
        int node = nb + r;
        if (node < NN) g_h[(size_t)node * HID + j] = gelu_f(acc[r]);
    }
}

// ---------------------------------------------------------------------------
// Scatter-add: warp per edge, vector red.global.add.v4.f32 (R1-proven)
// ---------------------------------------------------------------------------
__global__ __launch_bounds__(256) void scatter_kernel(
    const int* __restrict__ src, const int* __restrict__ dst)
{
    int idx = blockIdx.x * blockDim.x + threadIdx.x;
    int e = idx >> 5;
    if (e >= NE) return;
    int c = (idx & 31) * 4;
    int s = __ldg(src + e);
    int d = __ldg(dst + e);
    float4 v = *(const float4*)(g_h + (size_t)s * HID + c);
    float* p = g_agg + (size_t)d * HID + c;
    asm volatile("red.global.add.v4.f32 [%0], {%1, %2, %3, %4};"
                 :: "l"(p), "f"(v.x), "f"(v.y), "f"(v.z), "f"(v.w)
                 : "memory");
}

// ---------------------------------------------------------------------------
// Fused SAGE tail: mean@Wl + bl + h@Wr -> LN -> gelu -> +h -> g_h
// Phase 2: 2 adjacent cols/thread (float2 weight loads, coalesced),
// 4 rows/thread. Halves LDS traffic vs R1. Phases 1/3 identical to R1.
// ---------------------------------------------------------------------------
__global__ __launch_bounds__(128) void combine_kernel(
    const float* __restrict__ Wl, const float* __restrict__ bl,
    const float* __restrict__ Wr,
    const float* __restrict__ ng, const float* __restrict__ nbeta)
{
    __shared__ __align__(16) float sm_m[NPB][DIM];
    __shared__ __align__(16) float sm_r[NPB][DIM];
    int nb = blockIdx.x * NPB;
    int tid = threadIdx.x, w = tid >> 5, lane = tid & 31;

    // Phase 1: load mean (agg * 1/cnt) and root rows into smem (as R1)
#pragma unroll
    for (int rr = 0; rr < 2; rr++) {
        int r = w + rr * 4;
        int node = nb + r;
        int c = lane * 4;
        float4 a = make_float4(0.f, 0.f, 0.f, 0.f);
        float4 h = make_float4(0.f, 0.f, 0.f, 0.f);
        float inv = 0.f;
        if (node < NN) {
            inv = 1.0f / fmaxf(g_cnt[node], 1.0f);
            a = *(const float4*)(g_agg + (size_t)node * HID + c);
            h = *(const float4*)(g_h   + (size_t)node * HID + c);
        }
        a.x *= inv; a.y *= inv; a.z *= inv; a.w *= inv;
        *(float4*)&sm_m[r][c] = a;
        *(float4*)&sm_r[r][c] = h;
    }
    __syncthreads();

    // Phase 2: dual matvec; thread -> column pair cp..cp+1, rows rbase..rbase+3
    int cp    = (tid & 63) * 2;   // column pair base (0,2,...,126)
    int half  = tid >> 6;         // 0: rows 0-3, 1: rows 4-7
    int rbase = half * 4;

    float accx[4], accy[4];
#pragma unroll
    for (int r = 0; r < 4; r++) { accx[r] = 0.f; accy[r] = 0.f; }

#pragma unroll 4
    for (int k = 0; k < DIM; k += 4) {
        float2 wl0 = *(const float2*)(Wl + (size_t)(k + 0) * HID + cp);
        float2 wl1 = *(const float2*)(Wl + (size_t)(k + 1) * HID + cp);
        float2 wl2 = *(const float2*)(Wl + (size_t)(k + 2) * HID + cp);
        float2 wl3 = *(const float2*)(Wl + (size_t)(k + 3) * HID + cp);
        float2 wr0 = *(const float2*)(Wr + (size_t)(k + 0) * HID + cp);
        float2 wr1 = *(const float2*)(Wr + (size_t)(k + 1) * HID + cp);
        float2 wr2 = *(const float2*)(Wr + (size_t)(k + 2) * HID + cp);
        float2 wr3 = *(const float2*)(Wr + (size_t)(k + 3) * HID + cp);
#pragma unroll
        for (int r = 0; r < 4; r++) {
            float4 mv = *(const float4*)&sm_m[rbase + r][k];
            float4 hv = *(const float4*)&sm_r[rbase + r][k];
            accx[r] += mv.x * wl0.x + mv.y * wl1.x + mv.z * wl2.x + mv.w * wl3.x
                     + hv.x * wr0.x + hv.y * wr1.x + hv.z * wr2.x + hv.w * wr3.x;
            accy[r] += mv.x * wl0.y + mv.y * wl1.y + mv.z * wl2.y + mv.w * wl3.y
                     + hv.x * wr0.y + hv.y * wr1.y + hv.z * wr2.y + hv.w * wr3.y;
        }
    }
    __syncthreads();   // all reads of sm_m done before overwrite

    float2 bb = *(const float2*)(bl + cp);
#pragma unroll
    for (int r = 0; r < 4; r++) {
        float2 o2;
        o2.x = accx[r] + bb.x;
        o2.y = accy[r] + bb.y;
        *(float2*)&sm_m[rbase + r][cp] = o2;
    }
    __syncthreads();

    // Phase 3: per-row LN + gelu + residual, write back to g_h (as R1)
#pragma unroll
    for (int rr = 0; rr < 2; rr++) {
        int r = w + rr * 4;
        int node = nb + r;
        int c = lane * 4;
        float4 v = *(const float4*)&sm_m[r][c];
        float s  = v.x + v.y + v.z + v.w;
        float sq = v.x*v.x + v.y*v.y + v.z*v.z + v.w*v.w;
#pragma unroll
        for (int o = 16; o > 0; o >>= 1) {
            s  += __shfl_xor_sync(0xffffffffu, s,  o);
            sq += __shfl_xor_sync(0xffffffffu, sq, o);
        }
        float m    = s * (1.0f / HID);
        float rstd = rsqrtf(sq * (1.0f / HID) - m * m + 1e-5f);
        float4 hres = *(const float4*)&sm_r[r][c];
        float4 o4;
        o4.x = gelu_f((v.x - m) * rstd * ng[c + 0] + nbeta[c + 0]) + hres.x;
        o4.y = gelu_f((v.y - m) * rstd * ng[c + 1] + nbeta[c + 1]) + hres.y;
        o4.z = gelu_f((v.z - m) * rstd * ng[c + 2] + nbeta[c + 2]) + hres.z;
        o4.w = gelu_f((v.w - m) * rstd * ng[c + 3] + nbeta[c + 3]) + hres.w;
        if (node < NN) *(float4*)(g_h + (size_t)node * HID + c) = o4;
    }
}

// ---------------------------------------------------------------------------
// Fused: layernorm(h) @ out_proj + b -> out.  (identical to R1-proven version)
// ---------------------------------------------------------------------------
__global__ __launch_bounds__(128) void final_kernel(
    const float* __restrict__ lng, const float* __restrict__ lnb,
    const float* __restrict__ W,   const float* __restrict__ pb,
    float* __restrict__ out)
{
    __shared__ __align__(16) float sm[NPB][DIM];
    int nb = blockIdx.x * NPB;
    int tid = threadIdx.x, w = tid >> 5, lane = tid & 31;

#pragma unroll
    for (int rr = 0; rr < 2; rr++) {
        int r = w + rr * 4;
        int node = nb + r;
        int c = lane * 4;
        float4 v = make_float4(0.f, 0.f, 0.f, 0.f);
        if (node < NN) v = *(const float4*)(g_h + (size_t)node * HID + c);
        float s  = v.x + v.y + v.z + v.w;
        float sq = v.x*v.x + v.y*v.y + v.z*v.z + v.w*v.w;
#pragma unroll
        for (int o = 16; o > 0; o >>= 1) {
            s  += __shfl_xor_sync(0xffffffffu, s,  o);
            sq += __shfl_xor_sync(0xffffffffu, sq, o);
        }
        float m    = s * (1.0f / HID);
        float rstd = rsqrtf(sq * (1.0f / HID) - m * m + 1e-5f);
        float4 o4;
        o4.x = (v.x - m) * rstd * lng[c + 0] + lnb[c + 0];
        o4.y = (v.y - m) * rstd * lng[c + 1] + lnb[c + 1];
        o4.z = (v.z - m) * rstd * lng[c + 2] + lnb[c + 2];
        o4.w = (v.w - m) * rstd * lng[c + 3] + lnb[c + 3];
        *(float4*)&sm[r][c] = o4;
    }
    __syncthreads();

    int jj   = tid & 63;
    int half = tid >> 6;  // 0: rows 0-3, 1: rows 4-7
    float bias = pb[jj];
    float acc[4];
#pragma unroll
    for (int r = 0; r < 4; r++) acc[r] = bias;

#pragma unroll 4
    for (int k = 0; k < HID; k += 4) {
        float w0 = W[(k + 0) * ODIM + jj];
        float w1 = W[(k + 1) * ODIM + jj];
        float w2 = W[(k + 2) * ODIM + jj];
        float w3 = W[(k + 3) * ODIM + jj];
#pragma unroll
        for (int r = 0; r < 4; r++) {
            float4 hv = *(const float4*)&sm[half * 4 + r][k];
            acc[r] += hv.x * w0 + hv.y * w1 + hv.z * w2 + hv.w * w3;
        }
    }
#pragma unroll
    for (int r = 0; r < 4; r++) {
        int node = nb + half * 4 + r;
        if (node < NN) out[(size_t)node * ODIM + jj] = acc[r];
    }
}

// ---------------------------------------------------------------------------
extern "C" void kernel_launch(void* const* d_in, const int* in_sizes, int n_in,
                              void* d_out, int out_size)
{
    const float* x     = (const float*)d_in[0];
    const int*   ei    = (const int*)  d_in[1];
    const float* in_g  = (const float*)d_in[2];
    const float* in_b  = (const float*)d_in[3];
    const float* inW   = (const float*)d_in[4];
    const float* inPb  = (const float*)d_in[5];
    const float* Wl    = (const float*)d_in[6];
    const float* bl    = (const float*)d_in[7];
    const float* Wr    = (const float*)d_in[8];
    const float* ng    = (const float*)d_in[9];
    const float* nbta  = (const float*)d_in[10];
    const float* og    = (const float*)d_in[11];
    const float* ob    = (const float*)d_in[12];
    const float* oW    = (const float*)d_in[13];
    const float* oPb   = (const float*)d_in[14];
    float* out = (float*)d_out;

    const int* src = ei;
    const int* dst = ei + NE;

    void* cntp = nullptr;
    void* aggp = nullptr;
    cudaGetSymbolAddress(&cntp, g_cnt);
    cudaGetSymbolAddress(&aggp, g_agg);

    const int nblk = (NN + NPB - 1) / NPB;          // 6250
    const int sblk = (NE * 32 + 255) / 256;         // 100000

    cudaMemsetAsync(cntp, 0, NN * sizeof(float));
    count_kernel<<<(NE + 255) / 256, 256>>>(dst);
    input_kernel<<<nblk, 128>>>(x, in_g, in_b, inW, inPb);

    for (int l = 0; l < NL; l++) {
        cudaMemsetAsync(aggp, 0, (size_t)NN * HID * sizeof(float));
        scatter_kernel<<<sblk, 256>>>(src, dst);
        combine_kernel<<<nblk, 128>>>(Wl + (size_t)l * HID * HID,
                                      bl + l * HID,
                                      Wr + (size_t)l * HID * HID,
                                      ng + l * HID,
                                      nbta + l * HID);
    }

    final_kernel<<<nblk, 128>>>(og, ob, oW, oPb, out);
}

// round 9
// speedup vs baseline: 1.9155x; 1.0220x over previous
#include <cuda_runtime.h>
#include <math.h>

#define NN   50000
#define NE   800000
#define DIM  128
#define HID  128
#define ODIM 64
#define NL   3
#define NPB  8    // nodes per block (input/final kernels)
#define NPC  16   // nodes per block (combine kernel; 50000 % 16 == 0)

// Scratch (no allocation allowed)
__device__ float g_h[(size_t)NN * HID];
__device__ float g_agg[(size_t)NN * HID];
__device__ float g_cnt[NN];

__device__ __forceinline__ float gelu_f(float x) {
    return 0.5f * x * (1.0f + erff(x * 0.70710678118654752440f));
}

// ---------------------------------------------------------------------------
// In-degree count: one thread per edge
// ---------------------------------------------------------------------------
__global__ __launch_bounds__(256) void count_kernel(const int* __restrict__ dst) {
    int e = blockIdx.x * blockDim.x + threadIdx.x;
    if (e < NE) atomicAdd(&g_cnt[dst[e]], 1.0f);
}

// ---------------------------------------------------------------------------
// Fused: layernorm(x) -> @ in_proj + b -> gelu -> g_h
// 8 nodes / block of 128 threads. (identical to R1-proven version)
// ---------------------------------------------------------------------------
__global__ __launch_bounds__(128) void input_kernel(
    const float* __restrict__ x,
    const float* __restrict__ lng, const float* __restrict__ lnb,
    const float* __restrict__ W,   const float* __restrict__ pb)
{
    __shared__ __align__(16) float sm[NPB][DIM];
    int nb = blockIdx.x * NPB;
    int tid = threadIdx.x, w = tid >> 5, lane = tid & 31;

#pragma unroll
    for (int rr = 0; rr < 2; rr++) {
        int r = w + rr * 4;
        int node = nb + r;
        int c = lane * 4;
        float4 v = make_float4(0.f, 0.f, 0.f, 0.f);
        if (node < NN) v = *(const float4*)(x + (size_t)node * DIM + c);
        float s  = v.x + v.y + v.z + v.w;
        float sq = v.x*v.x + v.y*v.y + v.z*v.z + v.w*v.w;
#pragma unroll
        for (int o = 16; o > 0; o >>= 1) {
            s  += __shfl_xor_sync(0xffffffffu, s,  o);
            sq += __shfl_xor_sync(0xffffffffu, sq, o);
        }
        float m    = s * (1.0f / DIM);
        float rstd = rsqrtf(sq * (1.0f / DIM) - m * m + 1e-5f);
        float4 o4;
        o4.x = (v.x - m) * rstd * lng[c + 0] + lnb[c + 0];
        o4.y = (v.y - m) * rstd * lng[c + 1] + lnb[c + 1];
        o4.z = (v.z - m) * rstd * lng[c + 2] + lnb[c + 2];
        o4.w = (v.w - m) * rstd * lng[c + 3] + lnb[c + 3];
        *(float4*)&sm[r][c] = o4;
    }
    __syncthreads();

    int j = tid;
    float bias = pb[j];
    float acc[NPB];
#pragma unroll
    for (int r = 0; r < NPB; r++) acc[r] = bias;

#pragma unroll 4
    for (int k = 0; k < DIM; k += 4) {
        float w0 = W[(k + 0) * HID + j];
        float w1 = W[(k + 1) * HID + j];
        float w2 = W[(k + 2) * HID + j];
        float w3 = W[(k + 3) * HID + j];
#pragma unroll
        for (int r = 0; r < NPB; r++) {
            float4 hv = *(const float4*)&sm[r][k];
            acc[r] += hv.x * w0 + hv.y * w1 + hv.z * w2 + hv.w * w3;
        }
    }
#pragma unroll
    for (int r = 0; r < NPB; r++) {
        int node = nb + r;
        if (node < NN) g_h[(size_t)node * HID + j] = gelu_f(acc[r]);
    }
}

// ---------------------------------------------------------------------------
// Scatter-add: warp per edge, vector red.global.add.v4.f32 (R1-proven)
// ---------------------------------------------------------------------------
__global__ __launch_bounds__(256) void scatter_kernel(
    const int* __restrict__ src, const int* __restrict__ dst)
{
    int idx = blockIdx.x * blockDim.x + threadIdx.x;
    int e = idx >> 5;
    if (e >= NE) return;
    int c = (idx & 31) * 4;
    int s = __ldg(src + e);
    int d = __ldg(dst + e);
    float4 v = *(const float4*)(g_h + (size_t)s * HID + c);
    float* p = g_agg + (size_t)d * HID + c;
    asm volatile("red.global.add.v4.f32 [%0], {%1, %2, %3, %4};"
                 :: "l"(p), "f"(v.x), "f"(v.y), "f"(v.z), "f"(v.w)
                 : "memory");
}

// ---------------------------------------------------------------------------
// Fused SAGE tail: mean@Wl + bl + h@Wr -> LN -> gelu -> +h -> g_h
// NPC=16 rows/block. Phase 2: 4 cols/thread (float4 coalesced weight loads)
// x 4 rows/thread -> 128 FMA per 64 l1tex-wavefronts (ratio 2.0 vs 1.33 R8).
// ---------------------------------------------------------------------------
__global__ __launch_bounds__(128) void combine_kernel(
    const float* __restrict__ Wl, const float* __restrict__ bl,
    const float* __restrict__ Wr,
    const float* __restrict__ ng, const float* __restrict__ nbeta)
{
    __shared__ __align__(16) float sm_m[NPC][DIM];
    __shared__ __align__(16) float sm_r[NPC][DIM];
    int nb = blockIdx.x * NPC;
    int tid = threadIdx.x, w = tid >> 5, lane = tid & 31;

    // Phase 1: mean = agg/max(cnt,1), root = h -> smem (4 rows per warp)
#pragma unroll
    for (int rr = 0; rr < 4; rr++) {
        int r = w + rr * 4;
        int node = nb + r;           // NN % NPC == 0: no bounds check
        int c = lane * 4;
        float inv = 1.0f / fmaxf(g_cnt[node], 1.0f);
        float4 a = *(const float4*)(g_agg + (size_t)node * HID + c);
        float4 h = *(const float4*)(g_h   + (size_t)node * HID + c);
        a.x *= inv; a.y *= inv; a.z *= inv; a.w *= inv;
        *(float4*)&sm_m[r][c] = a;
        *(float4*)&sm_r[r][c] = h;
    }
    __syncthreads();

    // Phase 2: dual matvec; thread -> 4 cols (cp..cp+3) x 4 rows (rbase..+3)
    int cg    = tid & 31;        // 32 col-groups x 4 cols = 128 cols
    int rg    = tid >> 5;        // 4 row-groups x 4 rows = 16 rows
    int cp    = cg * 4;
    int rbase = rg * 4;

    float acc[4][4];             // [row][col]
#pragma unroll
    for (int r = 0; r < 4; r++)
#pragma unroll
        for (int cc = 0; cc < 4; cc++) acc[r][cc] = 0.f;

#pragma unroll 4
    for (int k = 0; k < DIM; k += 4) {
        float4 wl0 = *(const float4*)(Wl + (size_t)(k + 0) * HID + cp);
        float4 wl1 = *(const float4*)(Wl + (size_t)(k + 1) * HID + cp);
        float4 wl2 = *(const float4*)(Wl + (size_t)(k + 2) * HID + cp);
        float4 wl3 = *(const float4*)(Wl + (size_t)(k + 3) * HID + cp);
        float4 wr0 = *(const float4*)(Wr + (size_t)(k + 0) * HID + cp);
        float4 wr1 = *(const float4*)(Wr + (size_t)(k + 1) * HID + cp);
        float4 wr2 = *(const float4*)(Wr + (size_t)(k + 2) * HID + cp);
        float4 wr3 = *(const float4*)(Wr + (size_t)(k + 3) * HID + cp);
#pragma unroll
        for (int r = 0; r < 4; r++) {
            float4 mv = *(const float4*)&sm_m[rbase + r][k];
            float4 hv = *(const float4*)&sm_r[rbase + r][k];
            acc[r][0] += mv.x * wl0.x + mv.y * wl1.x + mv.z * wl2.x + mv.w * wl3.x
                       + hv.x * wr0.x + hv.y * wr1.x + hv.z * wr2.x + hv.w * wr3.x;
            acc[r][1] += mv.x * wl0.y + mv.y * wl1.y + mv.z * wl2.y + mv.w * wl3.y
                       + hv.x * wr0.y + hv.y * wr1.y + hv.z * wr2.y + hv.w * wr3.y;
            acc[r][2] += mv.x * wl0.z + mv.y * wl1.z + mv.z * wl2.z + mv.w * wl3.z
                       + hv.x * wr0.z + hv.y * wr1.z + hv.z * wr2.z + hv.w * wr3.z;
            acc[r][3] += mv.x * wl0.w + mv.y * wl1.w + mv.z * wl2.w + mv.w * wl3.w
                       + hv.x * wr0.w + hv.y * wr1.w + hv.z * wr2.w + hv.w * wr3.w;
        }
    }
    __syncthreads();   // all reads of sm_m done before overwrite

    float4 bb = *(const float4*)(bl + cp);
#pragma unroll
    for (int r = 0; r < 4; r++) {
        float4 o4;
        o4.x = acc[r][0] + bb.x;
        o4.y = acc[r][1] + bb.y;
        o4.z = acc[r][2] + bb.z;
        o4.w = acc[r][3] + bb.w;
        *(float4*)&sm_m[rbase + r][cp] = o4;
    }
    __syncthreads();

    // Phase 3: per-row LN + gelu + residual, write back to g_h (4 rows/warp)
#pragma unroll
    for (int rr = 0; rr < 4; rr++) {
        int r = w + rr * 4;
        int node = nb + r;
        int c = lane * 4;
        float4 v = *(const float4*)&sm_m[r][c];
        float s  = v.x + v.y + v.z + v.w;
        float sq = v.x*v.x + v.y*v.y + v.z*v.z + v.w*v.w;
#pragma unroll
        for (int o = 16; o > 0; o >>= 1) {
            s  += __shfl_xor_sync(0xffffffffu, s,  o);
            sq += __shfl_xor_sync(0xffffffffu, sq, o);
        }
        float m    = s * (1.0f / HID);
        float rstd = rsqrtf(sq * (1.0f / HID) - m * m + 1e-5f);
        float4 hres = *(const float4*)&sm_r[r][c];
        float4 o4;
        o4.x = gelu_f((v.x - m) * rstd * ng[c + 0] + nbeta[c + 0]) + hres.x;
        o4.y = gelu_f((v.y - m) * rstd * ng[c + 1] + nbeta[c + 1]) + hres.y;
        o4.z = gelu_f((v.z - m) * rstd * ng[c + 2] + nbeta[c + 2]) + hres.z;
        o4.w = gelu_f((v.w - m) * rstd * ng[c + 3] + nbeta[c + 3]) + hres.w;
        *(float4*)(g_h + (size_t)node * HID + c) = o4;
    }
}

// ---------------------------------------------------------------------------
// Fused: layernorm(h) @ out_proj + b -> out.  (identical to R1-proven version)
// ---------------------------------------------------------------------------
__global__ __launch_bounds__(128) void final_kernel(
    const float* __restrict__ lng, const float* __restrict__ lnb,
    const float* __restrict__ W,   const float* __restrict__ pb,
    float* __restrict__ out)
{
    __shared__ __align__(16) float sm[NPB][DIM];
    int nb = blockIdx.x * NPB;
    int tid = threadIdx.x, w = tid >> 5, lane = tid & 31;

#pragma unroll
    for (int rr = 0; rr < 2; rr++) {
        int r = w + rr * 4;
        int node = nb + r;
        int c = lane * 4;
        float4 v = make_float4(0.f, 0.f, 0.f, 0.f);
        if (node < NN) v = *(const float4*)(g_h + (size_t)node * HID + c);
        float s  = v.x + v.y + v.z + v.w;
        float sq = v.x*v.x + v.y*v.y + v.z*v.z + v.w*v.w;
#pragma unroll
        for (int o = 16; o > 0; o >>= 1) {
            s  += __shfl_xor_sync(0xffffffffu, s,  o);
            sq += __shfl_xor_sync(0xffffffffu, sq, o);
        }
        float m    = s * (1.0f / HID);
        float rstd = rsqrtf(sq * (1.0f / HID) - m * m + 1e-5f);
        float4 o4;
        o4.x = (v.x - m) * rstd * lng[c + 0] + lnb[c + 0];
        o4.y = (v.y - m) * rstd * lng[c + 1] + lnb[c + 1];
        o4.z = (v.z - m) * rstd * lng[c + 2] + lnb[c + 2];
        o4.w = (v.w - m) * rstd * lng[c + 3] + lnb[c + 3];
        *(float4*)&sm[r][c] = o4;
    }
    __syncthreads();

    int jj   = tid & 63;
    int half = tid >> 6;  // 0: rows 0-3, 1: rows 4-7
    float bias = pb[jj];
    float acc[4];
#pragma unroll
    for (int r = 0; r < 4; r++) acc[r] = bias;

#pragma unroll 4
    for (int k = 0; k < HID; k += 4) {
        float w0 = W[(k + 0) * ODIM + jj];
        float w1 = W[(k + 1) * ODIM + jj];
        float w2 = W[(k + 2) * ODIM + jj];
        float w3 = W[(k + 3) * ODIM + jj];
#pragma unroll
        for (int r = 0; r < 4; r++) {
            float4 hv = *(const float4*)&sm[half * 4 + r][k];
            acc[r] += hv.x * w0 + hv.y * w1 + hv.z * w2 + hv.w * w3;
        }
    }
#pragma unroll
    for (int r = 0; r < 4; r++) {
        int node = nb + half * 4 + r;
        if (node < NN) out[(size_t)node * ODIM + jj] = acc[r];
    }
}

// ---------------------------------------------------------------------------
extern "C" void kernel_launch(void* const* d_in, const int* in_sizes, int n_in,
                              void* d_out, int out_size)
{
    const float* x     = (const float*)d_in[0];
    const int*   ei    = (const int*)  d_in[1];
    const float* in_g  = (const float*)d_in[2];
    const float* in_b  = (const float*)d_in[3];
    const float* inW   = (const float*)d_in[4];
    const float* inPb  = (const float*)d_in[5];
    const float* Wl    = (const float*)d_in[6];
    const float* bl    = (const float*)d_in[7];
    const float* Wr    = (const float*)d_in[8];
    const float* ng    = (const float*)d_in[9];
    const float* nbta  = (const float*)d_in[10];
    const float* og    = (const float*)d_in[11];
    const float* ob    = (const float*)d_in[12];
    const float* oW    = (const float*)d_in[13];
    const float* oPb   = (const float*)d_in[14];
    float* out = (float*)d_out;

    const int* src = ei;
    const int* dst = ei + NE;

    void* cntp = nullptr;
    void* aggp = nullptr;
    cudaGetSymbolAddress(&cntp, g_cnt);
    cudaGetSymbolAddress(&aggp, g_agg);

    const int nblk  = (NN + NPB - 1) / NPB;          // 6250
    const int nblkc = NN / NPC;                      // 3125 (exact)
    const int sblk  = (NE * 32 + 255) / 256;         // 100000

    cudaMemsetAsync(cntp, 0, NN * sizeof(float));
    count_kernel<<<(NE + 255) / 256, 256>>>(dst);
    input_kernel<<<nblk, 128>>>(x, in_g, in_b, inW, inPb);

    for (int l = 0; l < NL; l++) {
        cudaMemsetAsync(aggp, 0, (size_t)NN * HID * sizeof(float));
        scatter_kernel<<<sblk, 256>>>(src, dst);
        combine_kernel<<<nblkc, 128>>>(Wl + (size_t)l * HID * HID,
                                       bl + l * HID,
                                       Wr + (size_t)l * HID * HID,
                                       ng + l * HID,
                                       nbta + l * HID);
    }

    final_kernel<<<nblk, 128>>>(og, ob, oW, oPb, out);
}